// round 15
// baseline (speedup 1.0000x reference)
#include <cuda_runtime.h>
#include <cuda_bf16.h>

#define NN 100000
#define NE 1600000
#define NG 512
#define NPAD 128   // row padding: GEMM tail blocks read (zeroed) pad rows safely

// ---------------------------------------------------------------------------
// Scratch (device globals; allocation is forbidden)
// g_hf1: [NN+pad][128] f32 = [x1(32) | agg0(32) | agg1(32) | agg2(32)]
// g_hf2: [NN+pad][256] f32 = [x2(64) | agg0(64) | agg1(64) | agg2(64)]
// g_x1h/g_x2h: bf16 shadow copies of x1/x2 — gather SOURCE only (halves traffic)
// g_wp1/g_wp2: packed tf32 B operand, layout [nt][kt][g][tig][2]
// ---------------------------------------------------------------------------
__device__ __align__(16) float g_hf1[(size_t)(NN + NPAD) * 128];
__device__ __align__(16) float g_hf2[(size_t)(NN + NPAD) * 256];
__device__ __align__(16) __nv_bfloat16 g_x1h[(size_t)(NN + NPAD) * 32];
__device__ __align__(16) __nv_bfloat16 g_x2h[(size_t)(NN + NPAD) * 64];
__device__ __align__(16) float g_wp1[64 * 128];
__device__ __align__(16) float g_wp2[64 * 256];
__device__ int   g_deg[NN];
__device__ int   g_off[NN];
__device__ int   g_part[128];
__device__ int   g_rank[NE];                      // per-edge rank within dst
__device__ int   g_eidx[NE];                      // src | (rel<<17)
__device__ float g_pool[NG * 64];

static __device__ __forceinline__ void red_add_v2(float* p, float2 v) {
    asm volatile("red.global.add.v2.f32 [%0], {%1,%2};"
                 :: "l"(p), "f"(v.x), "f"(v.y) : "memory");
}
static __device__ __forceinline__ void f4add(float4& a, float4 b) {
    a.x += b.x; a.y += b.y; a.z += b.z; a.w += b.w;
}
static __device__ __forceinline__ float4 f4scale(float4 a, float s) {
    return make_float4(a.x * s, a.y * s, a.z * s, a.w * s);
}
static __device__ __forceinline__ float4 bf4_to_f4(uint2 u) {
    float2 a = __bfloat1622float2(*(__nv_bfloat162*)&u.x);
    float2 b = __bfloat1622float2(*(__nv_bfloat162*)&u.y);
    return make_float4(a.x, a.y, b.x, b.y);
}
static __device__ __forceinline__ float tf32r(float v) {
    unsigned u;
    asm("cvt.rna.tf32.f32 %0, %1;" : "=r"(u) : "f"(v));
    return __uint_as_float(u);
}
static __device__ __forceinline__ float4 f4tf32(float4 v) {
    v.x = tf32r(v.x); v.y = tf32r(v.y); v.z = tf32r(v.z); v.w = tf32r(v.w);
    return v;
}
static __device__ __forceinline__ void mma_tf32(float* d, unsigned a0, unsigned a1,
                                                unsigned a2, unsigned a3,
                                                unsigned b0, unsigned b1) {
    asm volatile("mma.sync.aligned.m16n8k8.row.col.f32.tf32.tf32.f32 "
                 "{%0,%1,%2,%3}, {%4,%5,%6,%7}, {%8,%9}, {%0,%1,%2,%3};"
                 : "+f"(d[0]), "+f"(d[1]), "+f"(d[2]), "+f"(d[3])
                 : "r"(a0), "r"(a1), "r"(a2), "r"(a3), "r"(b0), "r"(b1));
}

// ---------------------------------------------------------------------------
// init: zero deg/pool + embedding + pre-MLP -> g_hf1 cols 0..31 (+bf16 shadow)
// ---------------------------------------------------------------------------
__global__ void init_embed_kernel(const int* __restrict__ nf,
                                  const float* __restrict__ se,
                                  const float* __restrict__ ce,
                                  const float* __restrict__ pw,
                                  const float* __restrict__ pb) {
    int idx = blockIdx.x * blockDim.x + threadIdx.x;
    int stride = gridDim.x * blockDim.x;
    for (int i = idx; i < NN; i += stride) g_deg[i] = 0;
    for (int i = idx; i < NG * 64; i += stride) g_pool[i] = 0.f;
    if (idx < NN * 32) {
        int i = idx >> 5, c = idx & 31;
        int s = nf[2 * i], col = nf[2 * i + 1];
        float acc = pb[c];
#pragma unroll
        for (int k = 0; k < 8; k++) acc = fmaf(se[s * 8 + k], pw[k * 32 + c], acc);
#pragma unroll
        for (int k = 0; k < 8; k++) acc = fmaf(ce[col * 8 + k], pw[(8 + k) * 32 + c], acc);
        float v = fmaxf(acc, 0.f);
        g_hf1[(size_t)i * 128 + c] = v;
        g_x1h[(size_t)i * 32 + c] = __float2bfloat16_rn(v);
    }
}

// ---------------------------------------------------------------------------
// Weight prep: pack stacked [root; rel] into mma B-fragment order, tf32-rounded.
// ---------------------------------------------------------------------------
static __device__ __forceinline__ void pack_one(float* dst, int p, int KT, int C,
                                                const float* root, const float* rel) {
    int nt = p / (KT * 64);
    int kt = (p / 64) % KT;
    int q = p & 63;
    int g = q >> 3, tig = (q & 7) >> 1, h = q & 1;
    int n = nt * 8 + g;
    int k = kt * 8 + tig + 4 * h;
    float v = (k < C) ? root[k * 64 + n] : rel[(k - C) * 64 + n];
    dst[p] = tf32r(v);
}

__global__ void prep_w_kernel(const float* __restrict__ root1, const float* __restrict__ rel1,
                              const float* __restrict__ root2, const float* __restrict__ rel2) {
    int idx = blockIdx.x * blockDim.x + threadIdx.x;
    if (idx < 64 * 128) {
        pack_one(g_wp1, idx, 16, 32, root1, rel1);
    } else if (idx < 64 * 128 + 64 * 256) {
        pack_one(g_wp2, idx - 64 * 128, 32, 64, root2, rel2);
    }
}

// ---------------------------------------------------------------------------
// CSR build: hist records per-edge rank -> fill needs no atomic
// ---------------------------------------------------------------------------
__global__ void hist_kernel(const int* __restrict__ ei) {
    int e = blockIdx.x * blockDim.x + threadIdx.x;
    if (e < NE) g_rank[e] = atomicAdd(&g_deg[ei[NE + e]], 1);
}

__global__ void scan_a_kernel() {
    __shared__ int wsum[32];
    int tid = threadIdx.x;
    int wid = tid >> 5, lane = tid & 31;
    int i = blockIdx.x * 1024 + tid;
    int v = (i < NN) ? g_deg[i] : 0;
    int s = v;
#pragma unroll
    for (int ofs = 1; ofs < 32; ofs <<= 1) {
        int t = __shfl_up_sync(0xffffffffu, s, ofs);
        if (lane >= ofs) s += t;
    }
    if (lane == 31) wsum[wid] = s;
    __syncthreads();
    if (wid == 0) {
        int ws = wsum[lane];
#pragma unroll
        for (int ofs = 1; ofs < 32; ofs <<= 1) {
            int t = __shfl_up_sync(0xffffffffu, ws, ofs);
            if (lane >= ofs) ws += t;
        }
        wsum[lane] = ws;
    }
    __syncthreads();
    int base = (wid > 0) ? wsum[wid - 1] : 0;
    if (i < NN) g_off[i] = base + s - v;
    if (tid == 1023) g_part[blockIdx.x] = base + s;
}

__global__ void scan_b_kernel() {
    __shared__ int ws[4];
    __shared__ int s_prefix;
    int tid = threadIdx.x;
    int b = blockIdx.x;
    if (tid < 128) {
        int v = (tid < b) ? g_part[tid] : 0;
#pragma unroll
        for (int ofs = 16; ofs > 0; ofs >>= 1)
            v += __shfl_down_sync(0xffffffffu, v, ofs);
        if ((tid & 31) == 0) ws[tid >> 5] = v;
    }
    __syncthreads();
    if (tid == 0) s_prefix = ws[0] + ws[1] + ws[2] + ws[3];
    __syncthreads();
    int prefix = s_prefix;
    int i = b * 1024 + tid;
    if (i < NN) g_off[i] += prefix;
}

__global__ void fill_kernel(const int* __restrict__ ei,
                            const int* __restrict__ et) {
    int e = blockIdx.x * blockDim.x + threadIdx.x;
    if (e >= NE) return;
    int dst = ei[NE + e];
    int pos = __ldg(&g_off[dst]) + g_rank[e];
    g_eidx[pos] = ei[e] | (et[e] << 17);
}

// ---------------------------------------------------------------------------
// gather1: 4 nodes/warp (8 lanes x 4 cols), bf16 source (64B/edge), f32 accum.
// ---------------------------------------------------------------------------
__global__ __launch_bounds__(256) void gather1_kernel() {
    int warp = blockIdx.x * 8 + (threadIdx.x >> 5);
    int lane = threadIdx.x & 31;
    int grp = lane >> 3, sub = lane & 7;
    int node = warp * 4 + grp;
    bool valid = node < NN;
    int off = valid ? g_off[node] : 0;
    int d   = valid ? g_deg[node] : 0;
    const int* ep = g_eidx + off;

    int dmax = d;
    dmax = max(dmax, __shfl_xor_sync(0xffffffffu, dmax, 8));
    dmax = max(dmax, __shfl_xor_sync(0xffffffffu, dmax, 16));

    float4 a0 = {0,0,0,0}, a1 = a0, a2 = a0;
    int c0 = 0, c1 = 0, c2 = 0;

    int pA = 0, pB = 0;
    if (0 < d) pA = __ldg(ep);
    if (1 < d) pB = __ldg(ep + 1);
    int i = 0;
    for (; i + 2 <= dmax; i += 2) {
        float4 vA = {0,0,0,0}, vB = vA;
        int rA = (i < d) ? (pA >> 17) : 3;
        int rB = (i + 1 < d) ? (pB >> 17) : 3;
        if (i < d)
            vA = bf4_to_f4(__ldg((const uint2*)(g_x1h + (size_t)(pA & 131071) * 32 + sub * 4)));
        if (i + 1 < d)
            vB = bf4_to_f4(__ldg((const uint2*)(g_x1h + (size_t)(pB & 131071) * 32 + sub * 4)));
        int pC = 0, pD = 0;
        if (i + 2 < d) pC = __ldg(ep + i + 2);
        if (i + 3 < d) pD = __ldg(ep + i + 3);
        if (rA == 0)      { f4add(a0, vA); c0++; }
        else if (rA == 1) { f4add(a1, vA); c1++; }
        else if (rA == 2) { f4add(a2, vA); c2++; }
        if (rB == 0)      { f4add(a0, vB); c0++; }
        else if (rB == 1) { f4add(a1, vB); c1++; }
        else if (rB == 2) { f4add(a2, vB); c2++; }
        pA = pC; pB = pD;
    }
    if (i < dmax && i < d) {
        int r = pA >> 17;
        float4 v = bf4_to_f4(__ldg((const uint2*)(g_x1h + (size_t)(pA & 131071) * 32 + sub * 4)));
        if (r == 0)      { f4add(a0, v); c0++; }
        else if (r == 1) { f4add(a1, v); c1++; }
        else             { f4add(a2, v); c2++; }
    }
    if (valid) {
        float* o = g_hf1 + (size_t)node * 128 + 32 + sub * 4;
        *(float4*)(o)      = f4scale(a0, 1.f / max(c0, 1));
        *(float4*)(o + 32) = f4scale(a1, 1.f / max(c1, 1));
        *(float4*)(o + 64) = f4scale(a2, 1.f / max(c2, 1));
    }
}

// ---------------------------------------------------------------------------
// gather2: 2 nodes/warp (16 lanes x 4 cols), bf16 source (128B/edge), f32 accum.
// ---------------------------------------------------------------------------
__global__ __launch_bounds__(256) void gather2_kernel() {
    int warp = blockIdx.x * 8 + (threadIdx.x >> 5);
    int lane = threadIdx.x & 31;
    int grp = lane >> 4, sub = lane & 15;
    int node = warp * 2 + grp;
    bool valid = node < NN;
    int off = valid ? g_off[node] : 0;
    int d   = valid ? g_deg[node] : 0;
    const int* ep = g_eidx + off;

    int dmax = max(d, __shfl_xor_sync(0xffffffffu, d, 16));

    float4 a0 = {0,0,0,0}, a1 = a0, a2 = a0;
    int c0 = 0, c1 = 0, c2 = 0;

    int pA = 0, pB = 0;
    if (0 < d) pA = __ldg(ep);
    if (1 < d) pB = __ldg(ep + 1);
    int i = 0;
    for (; i + 2 <= dmax; i += 2) {
        float4 vA = {0,0,0,0}, vB = vA;
        int rA = (i < d) ? (pA >> 17) : 3;
        int rB = (i + 1 < d) ? (pB >> 17) : 3;
        if (i < d)
            vA = bf4_to_f4(__ldg((const uint2*)(g_x2h + (size_t)(pA & 131071) * 64 + sub * 4)));
        if (i + 1 < d)
            vB = bf4_to_f4(__ldg((const uint2*)(g_x2h + (size_t)(pB & 131071) * 64 + sub * 4)));
        int pC = 0, pD = 0;
        if (i + 2 < d) pC = __ldg(ep + i + 2);
        if (i + 3 < d) pD = __ldg(ep + i + 3);
        if (rA == 0)      { f4add(a0, vA); c0++; }
        else if (rA == 1) { f4add(a1, vA); c1++; }
        else if (rA == 2) { f4add(a2, vA); c2++; }
        if (rB == 0)      { f4add(a0, vB); c0++; }
        else if (rB == 1) { f4add(a1, vB); c1++; }
        else if (rB == 2) { f4add(a2, vB); c2++; }
        pA = pC; pB = pD;
    }
    if (i < dmax && i < d) {
        int r = pA >> 17;
        float4 v = bf4_to_f4(__ldg((const uint2*)(g_x2h + (size_t)(pA & 131071) * 64 + sub * 4)));
        if (r == 0)      { f4add(a0, v); c0++; }
        else if (r == 1) { f4add(a1, v); c1++; }
        else             { f4add(a2, v); c2++; }
    }
    if (valid) {
        float* o = g_hf2 + (size_t)node * 256 + 64 + sub * 4;
        *(float4*)(o)       = f4scale(a0, 1.f / max(c0, 1));
        *(float4*)(o + 64)  = f4scale(a1, 1.f / max(c1, 1));
        *(float4*)(o + 128) = f4scale(a2, 1.f / max(c2, 1));
    }
}

// ---------------------------------------------------------------------------
// Hand-rolled tf32 mma GEMM (validated). LAYER1 epilogue also writes bf16 shadow.
// ---------------------------------------------------------------------------
template <int LAYER>
__global__ __launch_bounds__(256) void gemm_mma_kernel(const float* __restrict__ bias,
                                                       const int* __restrict__ batch) {
    constexpr int KK = (LAYER == 1) ? 128 : 256;
    constexpr int KT = KK / 8;
    const float* H  = (LAYER == 1) ? g_hf1 : g_hf2;
    const float* WP = (LAYER == 1) ? g_wp1 : g_wp2;

    extern __shared__ __align__(16) char dsm[];
    float* s_a = (float*)dsm;                            // [128][68]
    float* s_b = (float*)(dsm + 128 * 68 * 4);           // [64*KK] packed

    int tid = threadIdx.x;
    int wid = tid >> 5, lane = tid & 31;
    int g = lane >> 2, tig = lane & 3;
    int n0 = blockIdx.x * 128;

    for (int q = tid; q < 64 * KK / 4; q += 256)
        ((float4*)s_b)[q] = ((const float4*)WP)[q];

    float d[8][4];
#pragma unroll
    for (int nt = 0; nt < 8; nt++)
#pragma unroll
        for (int c = 0; c < 4; c++) d[nt][c] = 0.f;

    const unsigned* ua = (const unsigned*)s_a;
    int arow0 = (wid * 16 + g) * 68;
    int arow1 = arow0 + 8 * 68;

#pragma unroll
    for (int kc = 0; kc < KK; kc += 64) {
        __syncthreads();
#pragma unroll
        for (int it = 0; it < 8; it++) {
            int q = tid + it * 256;
            int row = q >> 4, c4 = (q & 15) * 4;
            float4 v = *(const float4*)(H + (size_t)(n0 + row) * KK + kc + c4);
            *(float4*)(s_a + row * 68 + c4) = f4tf32(v);
        }
        __syncthreads();

        int kt0 = kc >> 3;
#pragma unroll
        for (int k8 = 0; k8 < 8; k8++) {
            int kb = k8 * 8 + tig;
            unsigned a0 = ua[arow0 + kb];
            unsigned a1 = ua[arow1 + kb];
            unsigned a2 = ua[arow0 + kb + 4];
            unsigned a3 = ua[arow1 + kb + 4];
            int bbase = ((kt0 + k8) * 32 + g * 4 + tig) * 2;
#pragma unroll
            for (int nt = 0; nt < 8; nt++) {
                uint2 b = *(const uint2*)(s_b + nt * (KT * 64) + bbase);
                mma_tf32(d[nt], a0, a1, a2, a3, b.x, b.y);
            }
        }
    }

    int r0 = n0 + wid * 16 + g;
    int r1 = r0 + 8;
#pragma unroll
    for (int nt = 0; nt < 8; nt++) {
        int c = nt * 8 + tig * 2;
        float2 bb = *(const float2*)(bias + c);
        float2 v0 = make_float2(fmaxf(d[nt][0] + bb.x, 0.f), fmaxf(d[nt][1] + bb.y, 0.f));
        float2 v1 = make_float2(fmaxf(d[nt][2] + bb.x, 0.f), fmaxf(d[nt][3] + bb.y, 0.f));
        if (LAYER == 1) {
            if (r0 < NN) {
                *(float2*)(g_hf2 + (size_t)r0 * 256 + c) = v0;
                *(__nv_bfloat162*)(g_x2h + (size_t)r0 * 64 + c) = __float22bfloat162_rn(v0);
            }
            if (r1 < NN) {
                *(float2*)(g_hf2 + (size_t)r1 * 256 + c) = v1;
                *(__nv_bfloat162*)(g_x2h + (size_t)r1 * 64 + c) = __float22bfloat162_rn(v1);
            }
        } else {
            if (r0 < NN) red_add_v2(&g_pool[batch[r0] * 64 + c], v0);
            if (r1 < NN) red_add_v2(&g_pool[batch[r1] * 64 + c], v1);
        }
    }
}

// ---------------------------------------------------------------------------
// Classifier (graph counts via binary search on sorted batch)
// ---------------------------------------------------------------------------
static __device__ __forceinline__ int lower_bound(const int* b, int v) {
    int lo = 0, hi = NN;
    while (lo < hi) { int m = (lo + hi) >> 1; if (b[m] < v) lo = m + 1; else hi = m; }
    return lo;
}

__global__ void cls_kernel(const int* __restrict__ batch,
                           const float* __restrict__ cw,
                           const float* __restrict__ cb,
                           float* __restrict__ out) {
    int idx = blockIdx.x * blockDim.x + threadIdx.x;
    if (idx >= NG * 10) return;
    int g = idx / 10, c = idx - g * 10;
    int cnt = lower_bound(batch, g + 1) - lower_bound(batch, g);
    float inv = 1.f / max(cnt, 1);
    float acc = 0.f;
#pragma unroll
    for (int k = 0; k < 64; k++) acc = fmaf(g_pool[g * 64 + k], cw[k * 10 + c], acc);
    out[idx] = acc * inv + cb[c];
}

// ---------------------------------------------------------------------------
extern "C" void kernel_launch(void* const* d_in, const int* in_sizes, int n_in,
                              void* d_out, int out_size) {
    const int*   nf    = (const int*)d_in[0];
    const int*   ei    = (const int*)d_in[1];
    const int*   et    = (const int*)d_in[2];
    const int*   batch = (const int*)d_in[3];
    const float* se    = (const float*)d_in[4];
    const float* ce    = (const float*)d_in[5];
    const float* pw    = (const float*)d_in[6];
    const float* pb    = (const float*)d_in[7];
    const float* root1 = (const float*)d_in[8];
    const float* rel1  = (const float*)d_in[9];
    const float* bias1 = (const float*)d_in[10];
    const float* root2 = (const float*)d_in[11];
    const float* rel2  = (const float*)d_in[12];
    const float* bias2 = (const float*)d_in[13];
    const float* cw    = (const float*)d_in[14];
    const float* cb    = (const float*)d_in[15];
    float* out = (float*)d_out;

    const int SMEM1 = 128 * 68 * 4 + 64 * 128 * 4;   // 67584
    const int SMEM2 = 128 * 68 * 4 + 64 * 256 * 4;   // 100352
    cudaFuncSetAttribute(gemm_mma_kernel<1>, cudaFuncAttributeMaxDynamicSharedMemorySize, SMEM1);
    cudaFuncSetAttribute(gemm_mma_kernel<2>, cudaFuncAttributeMaxDynamicSharedMemorySize, SMEM2);

    init_embed_kernel<<<12500, 256>>>(nf, se, ce, pw, pb);
    prep_w_kernel<<<96, 256>>>(root1, rel1, root2, rel2);
    hist_kernel<<<(NE + 255) / 256, 256>>>(ei);
    scan_a_kernel<<<98, 1024>>>();
    scan_b_kernel<<<98, 1024>>>();
    fill_kernel<<<(NE + 255) / 256, 256>>>(ei, et);

    gather1_kernel<<<(NN + 31) / 32, 256>>>();
    gemm_mma_kernel<1><<<(NN + 127) / 128, 256, SMEM1>>>(bias1, batch);

    gather2_kernel<<<(NN + 15) / 16, 256>>>();
    gemm_mma_kernel<2><<<(NN + 127) / 128, 256, SMEM2>>>(bias2, batch);

    cls_kernel<<<20, 256>>>(batch, cw, cb, out);
}

// round 16
// speedup vs baseline: 1.0628x; 1.0628x over previous
#include <cuda_runtime.h>

#define NN 100000
#define NE 1600000
#define NG 512
#define NPAD 128   // row padding: GEMM tail blocks read (zeroed) pad rows safely

// ---------------------------------------------------------------------------
// Scratch (device globals; allocation is forbidden)
// g_hf1: [NN+pad][128] f32 = [x1(32) | agg0(32) | agg1(32) | agg2(32)]  (tf32-rounded)
// g_hf2: [NN+pad][256] f32 = [x2(64) | agg0(64) | agg1(64) | agg2(64)]  (tf32-rounded)
// g_wp1/g_wp2: packed tf32 B operand, layout [nt][kt][g][tig][2]
// ---------------------------------------------------------------------------
__device__ __align__(16) float g_hf1[(size_t)(NN + NPAD) * 128];
__device__ __align__(16) float g_hf2[(size_t)(NN + NPAD) * 256];
__device__ __align__(16) float g_wp1[64 * 128];
__device__ __align__(16) float g_wp2[64 * 256];
__device__ int   g_deg[NN];
__device__ int   g_off[NN];
__device__ int   g_part[128];
__device__ int   g_rank[NE];                      // per-edge rank within dst
__device__ int   g_eidx[NE];                      // src | (rel<<17)
__device__ float g_pool[NG * 64];

static __device__ __forceinline__ void red_add_v2(float* p, float2 v) {
    asm volatile("red.global.add.v2.f32 [%0], {%1,%2};"
                 :: "l"(p), "f"(v.x), "f"(v.y) : "memory");
}
static __device__ __forceinline__ void f4add(float4& a, float4 b) {
    a.x += b.x; a.y += b.y; a.z += b.z; a.w += b.w;
}
static __device__ __forceinline__ float4 f4scale(float4 a, float s) {
    return make_float4(a.x * s, a.y * s, a.z * s, a.w * s);
}
static __device__ __forceinline__ float tf32r(float v) {
    unsigned u;
    asm("cvt.rna.tf32.f32 %0, %1;" : "=r"(u) : "f"(v));
    return __uint_as_float(u);
}
static __device__ __forceinline__ float4 f4tf32(float4 v) {
    v.x = tf32r(v.x); v.y = tf32r(v.y); v.z = tf32r(v.z); v.w = tf32r(v.w);
    return v;
}
static __device__ __forceinline__ void mma_tf32(float* d, unsigned a0, unsigned a1,
                                                unsigned a2, unsigned a3,
                                                unsigned b0, unsigned b1) {
    asm volatile("mma.sync.aligned.m16n8k8.row.col.f32.tf32.tf32.f32 "
                 "{%0,%1,%2,%3}, {%4,%5,%6,%7}, {%8,%9}, {%0,%1,%2,%3};"
                 : "+f"(d[0]), "+f"(d[1]), "+f"(d[2]), "+f"(d[3])
                 : "r"(a0), "r"(a1), "r"(a2), "r"(a3), "r"(b0), "r"(b1));
}

// ---------------------------------------------------------------------------
// init: zero deg/pool + embedding + pre-MLP -> g_hf1 cols 0..31 (tf32-rounded)
// ---------------------------------------------------------------------------
__global__ void init_embed_kernel(const int* __restrict__ nf,
                                  const float* __restrict__ se,
                                  const float* __restrict__ ce,
                                  const float* __restrict__ pw,
                                  const float* __restrict__ pb) {
    int idx = blockIdx.x * blockDim.x + threadIdx.x;
    int stride = gridDim.x * blockDim.x;
    for (int i = idx; i < NN; i += stride) g_deg[i] = 0;
    for (int i = idx; i < NG * 64; i += stride) g_pool[i] = 0.f;
    if (idx < NN * 32) {
        int i = idx >> 5, c = idx & 31;
        int s = nf[2 * i], col = nf[2 * i + 1];
        float acc = pb[c];
#pragma unroll
        for (int k = 0; k < 8; k++) acc = fmaf(se[s * 8 + k], pw[k * 32 + c], acc);
#pragma unroll
        for (int k = 0; k < 8; k++) acc = fmaf(ce[col * 8 + k], pw[(8 + k) * 32 + c], acc);
        g_hf1[(size_t)i * 128 + c] = tf32r(fmaxf(acc, 0.f));
    }
}

// ---------------------------------------------------------------------------
// Weight prep: pack stacked [root; rel] into mma B-fragment order, tf32-rounded.
// ---------------------------------------------------------------------------
static __device__ __forceinline__ void pack_one(float* dst, int p, int KT, int C,
                                                const float* root, const float* rel) {
    int nt = p / (KT * 64);
    int kt = (p / 64) % KT;
    int q = p & 63;
    int g = q >> 3, tig = (q & 7) >> 1, h = q & 1;
    int n = nt * 8 + g;
    int k = kt * 8 + tig + 4 * h;
    float v = (k < C) ? root[k * 64 + n] : rel[(k - C) * 64 + n];
    dst[p] = tf32r(v);
}

__global__ void prep_w_kernel(const float* __restrict__ root1, const float* __restrict__ rel1,
                              const float* __restrict__ root2, const float* __restrict__ rel2) {
    int idx = blockIdx.x * blockDim.x + threadIdx.x;
    if (idx < 64 * 128) {
        pack_one(g_wp1, idx, 16, 32, root1, rel1);
    } else if (idx < 64 * 128 + 64 * 256) {
        pack_one(g_wp2, idx - 64 * 128, 32, 64, root2, rel2);
    }
}

// ---------------------------------------------------------------------------
// CSR build: hist records per-edge rank -> fill needs no atomic
// ---------------------------------------------------------------------------
__global__ void hist_kernel(const int* __restrict__ ei) {
    int e = blockIdx.x * blockDim.x + threadIdx.x;
    if (e < NE) g_rank[e] = atomicAdd(&g_deg[ei[NE + e]], 1);
}

__global__ void scan_a_kernel() {
    __shared__ int wsum[32];
    int tid = threadIdx.x;
    int wid = tid >> 5, lane = tid & 31;
    int i = blockIdx.x * 1024 + tid;
    int v = (i < NN) ? g_deg[i] : 0;
    int s = v;
#pragma unroll
    for (int ofs = 1; ofs < 32; ofs <<= 1) {
        int t = __shfl_up_sync(0xffffffffu, s, ofs);
        if (lane >= ofs) s += t;
    }
    if (lane == 31) wsum[wid] = s;
    __syncthreads();
    if (wid == 0) {
        int ws = wsum[lane];
#pragma unroll
        for (int ofs = 1; ofs < 32; ofs <<= 1) {
            int t = __shfl_up_sync(0xffffffffu, ws, ofs);
            if (lane >= ofs) ws += t;
        }
        wsum[lane] = ws;
    }
    __syncthreads();
    int base = (wid > 0) ? wsum[wid - 1] : 0;
    if (i < NN) g_off[i] = base + s - v;
    if (tid == 1023) g_part[blockIdx.x] = base + s;
}

__global__ void scan_b_kernel() {
    __shared__ int ws[4];
    __shared__ int s_prefix;
    int tid = threadIdx.x;
    int b = blockIdx.x;
    if (tid < 128) {
        int v = (tid < b) ? g_part[tid] : 0;
#pragma unroll
        for (int ofs = 16; ofs > 0; ofs >>= 1)
            v += __shfl_down_sync(0xffffffffu, v, ofs);
        if ((tid & 31) == 0) ws[tid >> 5] = v;
    }
    __syncthreads();
    if (tid == 0) s_prefix = ws[0] + ws[1] + ws[2] + ws[3];
    __syncthreads();
    int prefix = s_prefix;
    int i = b * 1024 + tid;
    if (i < NN) g_off[i] += prefix;
}

__global__ void fill_kernel(const int* __restrict__ ei,
                            const int* __restrict__ et) {
    int e = blockIdx.x * blockDim.x + threadIdx.x;
    if (e >= NE) return;
    int dst = ei[NE + e];
    int pos = __ldg(&g_off[dst]) + g_rank[e];
    g_eidx[pos] = ei[e] | (et[e] << 17);
}

// ---------------------------------------------------------------------------
// gather1: 4 nodes/warp (8 lanes x float4 over 32 cols), 2-edge pipeline.
// Epilogue rounds aggs to tf32 (issue slack here; removes cvt from GEMM).
// ---------------------------------------------------------------------------
__global__ __launch_bounds__(256) void gather1_kernel() {
    int warp = blockIdx.x * 8 + (threadIdx.x >> 5);
    int lane = threadIdx.x & 31;
    int grp = lane >> 3, sub = lane & 7;
    int node = warp * 4 + grp;
    bool valid = node < NN;
    int off = valid ? g_off[node] : 0;
    int d   = valid ? g_deg[node] : 0;
    const int* ep = g_eidx + off;

    int dmax = d;
    dmax = max(dmax, __shfl_xor_sync(0xffffffffu, dmax, 8));
    dmax = max(dmax, __shfl_xor_sync(0xffffffffu, dmax, 16));

    float4 a0 = {0,0,0,0}, a1 = a0, a2 = a0;
    int c0 = 0, c1 = 0, c2 = 0;

    int pA = 0, pB = 0;
    if (0 < d) pA = __ldg(ep);
    if (1 < d) pB = __ldg(ep + 1);
    int i = 0;
    for (; i + 2 <= dmax; i += 2) {
        float4 vA = {0,0,0,0}, vB = vA;
        int rA = (i < d) ? (pA >> 17) : 3;
        int rB = (i + 1 < d) ? (pB >> 17) : 3;
        if (i < d)     vA = *(const float4*)(g_hf1 + (size_t)(pA & 131071) * 128 + sub * 4);
        if (i + 1 < d) vB = *(const float4*)(g_hf1 + (size_t)(pB & 131071) * 128 + sub * 4);
        int pC = 0, pD = 0;
        if (i + 2 < d) pC = __ldg(ep + i + 2);
        if (i + 3 < d) pD = __ldg(ep + i + 3);
        if (rA == 0)      { f4add(a0, vA); c0++; }
        else if (rA == 1) { f4add(a1, vA); c1++; }
        else if (rA == 2) { f4add(a2, vA); c2++; }
        if (rB == 0)      { f4add(a0, vB); c0++; }
        else if (rB == 1) { f4add(a1, vB); c1++; }
        else if (rB == 2) { f4add(a2, vB); c2++; }
        pA = pC; pB = pD;
    }
    if (i < dmax && i < d) {
        int r = pA >> 17;
        float4 v = *(const float4*)(g_hf1 + (size_t)(pA & 131071) * 128 + sub * 4);
        if (r == 0)      { f4add(a0, v); c0++; }
        else if (r == 1) { f4add(a1, v); c1++; }
        else             { f4add(a2, v); c2++; }
    }
    if (valid) {
        float* o = g_hf1 + (size_t)node * 128 + 32 + sub * 4;
        *(float4*)(o)      = f4tf32(f4scale(a0, 1.f / max(c0, 1)));
        *(float4*)(o + 32) = f4tf32(f4scale(a1, 1.f / max(c1, 1)));
        *(float4*)(o + 64) = f4tf32(f4scale(a2, 1.f / max(c2, 1)));
    }
}

// ---------------------------------------------------------------------------
// gather2: 2 nodes/warp (16 lanes x float4 over 64 cols), 2-edge pipeline.
// Epilogue rounds aggs to tf32.
// ---------------------------------------------------------------------------
__global__ __launch_bounds__(256) void gather2_kernel() {
    int warp = blockIdx.x * 8 + (threadIdx.x >> 5);
    int lane = threadIdx.x & 31;
    int grp = lane >> 4, sub = lane & 15;
    int node = warp * 2 + grp;
    bool valid = node < NN;
    int off = valid ? g_off[node] : 0;
    int d   = valid ? g_deg[node] : 0;
    const int* ep = g_eidx + off;

    int dmax = max(d, __shfl_xor_sync(0xffffffffu, d, 16));

    float4 a0 = {0,0,0,0}, a1 = a0, a2 = a0;
    int c0 = 0, c1 = 0, c2 = 0;

    int pA = 0, pB = 0;
    if (0 < d) pA = __ldg(ep);
    if (1 < d) pB = __ldg(ep + 1);
    int i = 0;
    for (; i + 2 <= dmax; i += 2) {
        float4 vA = {0,0,0,0}, vB = vA;
        int rA = (i < d) ? (pA >> 17) : 3;
        int rB = (i + 1 < d) ? (pB >> 17) : 3;
        if (i < d)     vA = *(const float4*)(g_hf2 + (size_t)(pA & 131071) * 256 + sub * 4);
        if (i + 1 < d) vB = *(const float4*)(g_hf2 + (size_t)(pB & 131071) * 256 + sub * 4);
        int pC = 0, pD = 0;
        if (i + 2 < d) pC = __ldg(ep + i + 2);
        if (i + 3 < d) pD = __ldg(ep + i + 3);
        if (rA == 0)      { f4add(a0, vA); c0++; }
        else if (rA == 1) { f4add(a1, vA); c1++; }
        else if (rA == 2) { f4add(a2, vA); c2++; }
        if (rB == 0)      { f4add(a0, vB); c0++; }
        else if (rB == 1) { f4add(a1, vB); c1++; }
        else if (rB == 2) { f4add(a2, vB); c2++; }
        pA = pC; pB = pD;
    }
    if (i < dmax && i < d) {
        int r = pA >> 17;
        float4 v = *(const float4*)(g_hf2 + (size_t)(pA & 131071) * 256 + sub * 4);
        if (r == 0)      { f4add(a0, v); c0++; }
        else if (r == 1) { f4add(a1, v); c1++; }
        else             { f4add(a2, v); c2++; }
    }
    if (valid) {
        float* o = g_hf2 + (size_t)node * 256 + 64 + sub * 4;
        *(float4*)(o)       = f4tf32(f4scale(a0, 1.f / max(c0, 1)));
        *(float4*)(o + 64)  = f4tf32(f4scale(a1, 1.f / max(c1, 1)));
        *(float4*)(o + 128) = f4tf32(f4scale(a2, 1.f / max(c2, 1)));
    }
}

// ---------------------------------------------------------------------------
// Hand-rolled tf32 mma GEMM. A is pre-rounded by producers -> staging is a
// plain float4 copy (no cvt). LAYER1 epilogue stores tf32-rounded x2.
// ---------------------------------------------------------------------------
template <int LAYER>
__global__ __launch_bounds__(256) void gemm_mma_kernel(const float* __restrict__ bias,
                                                       const int* __restrict__ batch) {
    constexpr int KK = (LAYER == 1) ? 128 : 256;
    constexpr int KT = KK / 8;
    const float* H  = (LAYER == 1) ? g_hf1 : g_hf2;
    const float* WP = (LAYER == 1) ? g_wp1 : g_wp2;

    extern __shared__ __align__(16) char dsm[];
    float* s_a = (float*)dsm;                            // [128][68]
    float* s_b = (float*)(dsm + 128 * 68 * 4);           // [64*KK] packed

    int tid = threadIdx.x;
    int wid = tid >> 5, lane = tid & 31;
    int g = lane >> 2, tig = lane & 3;
    int n0 = blockIdx.x * 128;

    for (int q = tid; q < 64 * KK / 4; q += 256)
        ((float4*)s_b)[q] = ((const float4*)WP)[q];

    float d[8][4];
#pragma unroll
    for (int nt = 0; nt < 8; nt++)
#pragma unroll
        for (int c = 0; c < 4; c++) d[nt][c] = 0.f;

    const unsigned* ua = (const unsigned*)s_a;
    int arow0 = (wid * 16 + g) * 68;
    int arow1 = arow0 + 8 * 68;

#pragma unroll
    for (int kc = 0; kc < KK; kc += 64) {
        __syncthreads();
#pragma unroll
        for (int it = 0; it < 8; it++) {
            int q = tid + it * 256;
            int row = q >> 4, c4 = (q & 15) * 4;
            *(float4*)(s_a + row * 68 + c4) =
                *(const float4*)(H + (size_t)(n0 + row) * KK + kc + c4);
        }
        __syncthreads();

        int kt0 = kc >> 3;
#pragma unroll
        for (int k8 = 0; k8 < 8; k8++) {
            int kb = k8 * 8 + tig;
            unsigned a0 = ua[arow0 + kb];
            unsigned a1 = ua[arow1 + kb];
            unsigned a2 = ua[arow0 + kb + 4];
            unsigned a3 = ua[arow1 + kb + 4];
            int bbase = ((kt0 + k8) * 32 + g * 4 + tig) * 2;
#pragma unroll
            for (int nt = 0; nt < 8; nt++) {
                uint2 b = *(const uint2*)(s_b + nt * (KT * 64) + bbase);
                mma_tf32(d[nt], a0, a1, a2, a3, b.x, b.y);
            }
        }
    }

    int r0 = n0 + wid * 16 + g;
    int r1 = r0 + 8;
#pragma unroll
    for (int nt = 0; nt < 8; nt++) {
        int c = nt * 8 + tig * 2;
        float2 bb = *(const float2*)(bias + c);
        float2 v0 = make_float2(fmaxf(d[nt][0] + bb.x, 0.f), fmaxf(d[nt][1] + bb.y, 0.f));
        float2 v1 = make_float2(fmaxf(d[nt][2] + bb.x, 0.f), fmaxf(d[nt][3] + bb.y, 0.f));
        if (LAYER == 1) {
            if (r0 < NN) *(float2*)(g_hf2 + (size_t)r0 * 256 + c) =
                make_float2(tf32r(v0.x), tf32r(v0.y));
            if (r1 < NN) *(float2*)(g_hf2 + (size_t)r1 * 256 + c) =
                make_float2(tf32r(v1.x), tf32r(v1.y));
        } else {
            if (r0 < NN) red_add_v2(&g_pool[batch[r0] * 64 + c], v0);
            if (r1 < NN) red_add_v2(&g_pool[batch[r1] * 64 + c], v1);
        }
    }
}

// ---------------------------------------------------------------------------
// Classifier (graph counts via binary search on sorted batch)
// ---------------------------------------------------------------------------
static __device__ __forceinline__ int lower_bound(const int* b, int v) {
    int lo = 0, hi = NN;
    while (lo < hi) { int m = (lo + hi) >> 1; if (b[m] < v) lo = m + 1; else hi = m; }
    return lo;
}

__global__ void cls_kernel(const int* __restrict__ batch,
                           const float* __restrict__ cw,
                           const float* __restrict__ cb,
                           float* __restrict__ out) {
    int idx = blockIdx.x * blockDim.x + threadIdx.x;
    if (idx >= NG * 10) return;
    int g = idx / 10, c = idx - g * 10;
    int cnt = lower_bound(batch, g + 1) - lower_bound(batch, g);
    float inv = 1.f / max(cnt, 1);
    float acc = 0.f;
#pragma unroll
    for (int k = 0; k < 64; k++) acc = fmaf(g_pool[g * 64 + k], cw[k * 10 + c], acc);
    out[idx] = acc * inv + cb[c];
}

// ---------------------------------------------------------------------------
extern "C" void kernel_launch(void* const* d_in, const int* in_sizes, int n_in,
                              void* d_out, int out_size) {
    const int*   nf    = (const int*)d_in[0];
    const int*   ei    = (const int*)d_in[1];
    const int*   et    = (const int*)d_in[2];
    const int*   batch = (const int*)d_in[3];
    const float* se    = (const float*)d_in[4];
    const float* ce    = (const float*)d_in[5];
    const float* pw    = (const float*)d_in[6];
    const float* pb    = (const float*)d_in[7];
    const float* root1 = (const float*)d_in[8];
    const float* rel1  = (const float*)d_in[9];
    const float* bias1 = (const float*)d_in[10];
    const float* root2 = (const float*)d_in[11];
    const float* rel2  = (const float*)d_in[12];
    const float* bias2 = (const float*)d_in[13];
    const float* cw    = (const float*)d_in[14];
    const float* cb    = (const float*)d_in[15];
    float* out = (float*)d_out;

    const int SMEM1 = 128 * 68 * 4 + 64 * 128 * 4;   // 67584
    const int SMEM2 = 128 * 68 * 4 + 64 * 256 * 4;   // 100352
    cudaFuncSetAttribute(gemm_mma_kernel<1>, cudaFuncAttributeMaxDynamicSharedMemorySize, SMEM1);
    cudaFuncSetAttribute(gemm_mma_kernel<2>, cudaFuncAttributeMaxDynamicSharedMemorySize, SMEM2);

    init_embed_kernel<<<12500, 256>>>(nf, se, ce, pw, pb);
    prep_w_kernel<<<96, 256>>>(root1, rel1, root2, rel2);
    hist_kernel<<<(NE + 255) / 256, 256>>>(ei);
    scan_a_kernel<<<98, 1024>>>();
    scan_b_kernel<<<98, 1024>>>();
    fill_kernel<<<(NE + 255) / 256, 256>>>(ei, et);

    gather1_kernel<<<(NN + 31) / 32, 256>>>();
    gemm_mma_kernel<1><<<(NN + 127) / 128, 256, SMEM1>>>(bias1, batch);

    gather2_kernel<<<(NN + 15) / 16, 256>>>();
    gemm_mma_kernel<2><<<(NN + 127) / 128, 256, SMEM2>>>(bias2, batch);

    cls_kernel<<<20, 256>>>(batch, cw, cb, out);
}

// round 17
// speedup vs baseline: 1.1052x; 1.0399x over previous
#include <cuda_runtime.h>

#define NN 100000
#define NE 1600000
#define NG 512
#define NPAD 128   // row padding: GEMM tail blocks read (zeroed) pad rows safely

// ---------------------------------------------------------------------------
// Scratch (device globals; allocation is forbidden)
// g_hf1: [NN+pad][128] f32 = [x1(32) | agg0(32) | agg1(32) | agg2(32)]  (tf32-rounded)
// g_hf2: [NN+pad][256] f32 = [x2(64) | agg0(64) | agg1(64) | agg2(64)]  (tf32-rounded)
// g_wp1/g_wp2: packed tf32 B operand, layout [nt][kt][g][tig][2]
// g_deg3: per-(dst,rel) counts; edges sorted by rel within dst -> branch-free gather
// ---------------------------------------------------------------------------
__device__ __align__(16) float g_hf1[(size_t)(NN + NPAD) * 128];
__device__ __align__(16) float g_hf2[(size_t)(NN + NPAD) * 256];
__device__ __align__(16) float g_wp1[64 * 128];
__device__ __align__(16) float g_wp2[64 * 256];
__device__ int   g_deg3[3 * NN];
__device__ int   g_off[NN];
__device__ int   g_part[128];
__device__ int   g_rank[NE];                      // rank within (dst,rel)
__device__ int   g_eidx[NE];                      // src only (rel implicit by segment)
__device__ float g_pool[NG * 64];

static __device__ __forceinline__ void red_add_v2(float* p, float2 v) {
    asm volatile("red.global.add.v2.f32 [%0], {%1,%2};"
                 :: "l"(p), "f"(v.x), "f"(v.y) : "memory");
}
static __device__ __forceinline__ void f4add(float4& a, float4 b) {
    a.x += b.x; a.y += b.y; a.z += b.z; a.w += b.w;
}
static __device__ __forceinline__ float4 f4scale(float4 a, float s) {
    return make_float4(a.x * s, a.y * s, a.z * s, a.w * s);
}
static __device__ __forceinline__ float tf32r(float v) {
    unsigned u;
    asm("cvt.rna.tf32.f32 %0, %1;" : "=r"(u) : "f"(v));
    return __uint_as_float(u);
}
static __device__ __forceinline__ float4 f4tf32(float4 v) {
    v.x = tf32r(v.x); v.y = tf32r(v.y); v.z = tf32r(v.z); v.w = tf32r(v.w);
    return v;
}
static __device__ __forceinline__ void mma_tf32(float* d, unsigned a0, unsigned a1,
                                                unsigned a2, unsigned a3,
                                                unsigned b0, unsigned b1) {
    asm volatile("mma.sync.aligned.m16n8k8.row.col.f32.tf32.tf32.f32 "
                 "{%0,%1,%2,%3}, {%4,%5,%6,%7}, {%8,%9}, {%0,%1,%2,%3};"
                 : "+f"(d[0]), "+f"(d[1]), "+f"(d[2]), "+f"(d[3])
                 : "r"(a0), "r"(a1), "r"(a2), "r"(a3), "r"(b0), "r"(b1));
}

// ---------------------------------------------------------------------------
// init: zero deg3/pool + embedding + pre-MLP -> g_hf1 cols 0..31 (tf32-rounded)
// ---------------------------------------------------------------------------
__global__ void init_embed_kernel(const int* __restrict__ nf,
                                  const float* __restrict__ se,
                                  const float* __restrict__ ce,
                                  const float* __restrict__ pw,
                                  const float* __restrict__ pb) {
    int idx = blockIdx.x * blockDim.x + threadIdx.x;
    int stride = gridDim.x * blockDim.x;
    for (int i = idx; i < 3 * NN; i += stride) g_deg3[i] = 0;
    for (int i = idx; i < NG * 64; i += stride) g_pool[i] = 0.f;
    if (idx < NN * 32) {
        int i = idx >> 5, c = idx & 31;
        int s = nf[2 * i], col = nf[2 * i + 1];
        float acc = pb[c];
#pragma unroll
        for (int k = 0; k < 8; k++) acc = fmaf(se[s * 8 + k], pw[k * 32 + c], acc);
#pragma unroll
        for (int k = 0; k < 8; k++) acc = fmaf(ce[col * 8 + k], pw[(8 + k) * 32 + c], acc);
        g_hf1[(size_t)i * 128 + c] = tf32r(fmaxf(acc, 0.f));
    }
}

// ---------------------------------------------------------------------------
// Weight prep: pack stacked [root; rel] into mma B-fragment order, tf32-rounded.
// ---------------------------------------------------------------------------
static __device__ __forceinline__ void pack_one(float* dst, int p, int KT, int C,
                                                const float* root, const float* rel) {
    int nt = p / (KT * 64);
    int kt = (p / 64) % KT;
    int q = p & 63;
    int g = q >> 3, tig = (q & 7) >> 1, h = q & 1;
    int n = nt * 8 + g;
    int k = kt * 8 + tig + 4 * h;
    float v = (k < C) ? root[k * 64 + n] : rel[(k - C) * 64 + n];
    dst[p] = tf32r(v);
}

__global__ void prep_w_kernel(const float* __restrict__ root1, const float* __restrict__ rel1,
                              const float* __restrict__ root2, const float* __restrict__ rel2) {
    int idx = blockIdx.x * blockDim.x + threadIdx.x;
    if (idx < 64 * 128) {
        pack_one(g_wp1, idx, 16, 32, root1, rel1);
    } else if (idx < 64 * 128 + 64 * 256) {
        pack_one(g_wp2, idx - 64 * 128, 32, 64, root2, rel2);
    }
}

// ---------------------------------------------------------------------------
// CSR build: per-(dst,rel) counts; within-dst rel-sorted fill, no atomics.
// ---------------------------------------------------------------------------
__global__ void hist_kernel(const int* __restrict__ ei, const int* __restrict__ et) {
    int e = blockIdx.x * blockDim.x + threadIdx.x;
    if (e < NE) g_rank[e] = atomicAdd(&g_deg3[ei[NE + e] * 3 + et[e]], 1);
}

__global__ void scan_a_kernel() {
    __shared__ int wsum[32];
    int tid = threadIdx.x;
    int wid = tid >> 5, lane = tid & 31;
    int i = blockIdx.x * 1024 + tid;
    int v = 0;
    if (i < NN) v = g_deg3[i * 3] + g_deg3[i * 3 + 1] + g_deg3[i * 3 + 2];
    int s = v;
#pragma unroll
    for (int ofs = 1; ofs < 32; ofs <<= 1) {
        int t = __shfl_up_sync(0xffffffffu, s, ofs);
        if (lane >= ofs) s += t;
    }
    if (lane == 31) wsum[wid] = s;
    __syncthreads();
    if (wid == 0) {
        int ws = wsum[lane];
#pragma unroll
        for (int ofs = 1; ofs < 32; ofs <<= 1) {
            int t = __shfl_up_sync(0xffffffffu, ws, ofs);
            if (lane >= ofs) ws += t;
        }
        wsum[lane] = ws;
    }
    __syncthreads();
    int base = (wid > 0) ? wsum[wid - 1] : 0;
    if (i < NN) g_off[i] = base + s - v;
    if (tid == 1023) g_part[blockIdx.x] = base + s;
}

__global__ void scan_b_kernel() {
    __shared__ int ws[4];
    __shared__ int s_prefix;
    int tid = threadIdx.x;
    int b = blockIdx.x;
    if (tid < 128) {
        int v = (tid < b) ? g_part[tid] : 0;
#pragma unroll
        for (int ofs = 16; ofs > 0; ofs >>= 1)
            v += __shfl_down_sync(0xffffffffu, v, ofs);
        if ((tid & 31) == 0) ws[tid >> 5] = v;
    }
    __syncthreads();
    if (tid == 0) s_prefix = ws[0] + ws[1] + ws[2] + ws[3];
    __syncthreads();
    int prefix = s_prefix;
    int i = b * 1024 + tid;
    if (i < NN) g_off[i] += prefix;
}

__global__ void fill_kernel(const int* __restrict__ ei,
                            const int* __restrict__ et) {
    int e = blockIdx.x * blockDim.x + threadIdx.x;
    if (e >= NE) return;
    int dst = ei[NE + e];
    int r = et[e];
    int base = __ldg(&g_off[dst]);
    if (r > 0) base += __ldg(&g_deg3[dst * 3]);
    if (r > 1) base += __ldg(&g_deg3[dst * 3 + 1]);
    g_eidx[base + g_rank[e]] = ei[e];
}

// ---------------------------------------------------------------------------
// Branch-free segment accumulate (2-deep pipeline). d per lane-group; dmax is
// warp-consistent max so the warp stays converged.
// ---------------------------------------------------------------------------
template <int C>
static __device__ __forceinline__ float4 seg_gather(const float* __restrict__ X,
                                                    const int* __restrict__ ep,
                                                    int d, int dmax, int sub) {
    float4 a = {0, 0, 0, 0};
    int p0 = 0, p1 = 0;
    if (0 < d) p0 = __ldg(ep);
    if (1 < d) p1 = __ldg(ep + 1);
    int i = 0;
    for (; i + 2 <= dmax; i += 2) {
        float4 v0 = {0, 0, 0, 0}, v1 = v0;
        if (i < d)     v0 = *(const float4*)(X + (size_t)p0 * C + sub * 4);
        if (i + 1 < d) v1 = *(const float4*)(X + (size_t)p1 * C + sub * 4);
        int q0 = 0, q1 = 0;
        if (i + 2 < d) q0 = __ldg(ep + i + 2);
        if (i + 3 < d) q1 = __ldg(ep + i + 3);
        f4add(a, v0);
        f4add(a, v1);
        p0 = q0; p1 = q1;
    }
    if (i < dmax && i < d) {
        float4 v = *(const float4*)(X + (size_t)p0 * C + sub * 4);
        f4add(a, v);
    }
    return a;
}

// ---------------------------------------------------------------------------
// gather1: 4 nodes/warp (8 lanes x float4 over 32 cols); 3 rel-segment loops.
// Reads x from g_hf1 cols 0..31 (row pitch 128): C=128 template param.
// ---------------------------------------------------------------------------
__global__ __launch_bounds__(256) void gather1_kernel() {
    int warp = blockIdx.x * 8 + (threadIdx.x >> 5);
    int lane = threadIdx.x & 31;
    int sub = lane & 7;
    int node = warp * 4 + (lane >> 3);
    bool valid = node < NN;
    int off = valid ? g_off[node] : 0;
    int d0 = 0, d1 = 0, d2 = 0;
    if (valid) {
        d0 = g_deg3[node * 3];
        d1 = g_deg3[node * 3 + 1];
        d2 = g_deg3[node * 3 + 2];
    }
    const int* ep = g_eidx + off;

#define WMAX(x) ({ int t_ = (x); \
    t_ = max(t_, __shfl_xor_sync(0xffffffffu, t_, 8)); \
    max(t_, __shfl_xor_sync(0xffffffffu, t_, 16)); })
    int m0 = WMAX(d0), m1 = WMAX(d1), m2 = WMAX(d2);
#undef WMAX

    float4 a0 = seg_gather<128>(g_hf1, ep, d0, m0, sub);
    float4 a1 = seg_gather<128>(g_hf1, ep + d0, d1, m1, sub);
    float4 a2 = seg_gather<128>(g_hf1, ep + d0 + d1, d2, m2, sub);

    if (valid) {
        float* o = g_hf1 + (size_t)node * 128 + 32 + sub * 4;
        *(float4*)(o)      = f4tf32(f4scale(a0, 1.f / max(d0, 1)));
        *(float4*)(o + 32) = f4tf32(f4scale(a1, 1.f / max(d1, 1)));
        *(float4*)(o + 64) = f4tf32(f4scale(a2, 1.f / max(d2, 1)));
    }
}

// ---------------------------------------------------------------------------
// gather2: 2 nodes/warp (16 lanes x float4 over 64 cols); 3 rel-segment loops.
// Reads x2 from g_hf2 cols 0..63 (row pitch 256): C=256.
// ---------------------------------------------------------------------------
__global__ __launch_bounds__(256) void gather2_kernel() {
    int warp = blockIdx.x * 8 + (threadIdx.x >> 5);
    int lane = threadIdx.x & 31;
    int sub = lane & 15;
    int node = warp * 2 + (lane >> 4);
    bool valid = node < NN;
    int off = valid ? g_off[node] : 0;
    int d0 = 0, d1 = 0, d2 = 0;
    if (valid) {
        d0 = g_deg3[node * 3];
        d1 = g_deg3[node * 3 + 1];
        d2 = g_deg3[node * 3 + 2];
    }
    const int* ep = g_eidx + off;

    int m0 = max(d0, __shfl_xor_sync(0xffffffffu, d0, 16));
    int m1 = max(d1, __shfl_xor_sync(0xffffffffu, d1, 16));
    int m2 = max(d2, __shfl_xor_sync(0xffffffffu, d2, 16));

    float4 a0 = seg_gather<256>(g_hf2, ep, d0, m0, sub);
    float4 a1 = seg_gather<256>(g_hf2, ep + d0, d1, m1, sub);
    float4 a2 = seg_gather<256>(g_hf2, ep + d0 + d1, d2, m2, sub);

    if (valid) {
        float* o = g_hf2 + (size_t)node * 256 + 64 + sub * 4;
        *(float4*)(o)       = f4tf32(f4scale(a0, 1.f / max(d0, 1)));
        *(float4*)(o + 64)  = f4tf32(f4scale(a1, 1.f / max(d1, 1)));
        *(float4*)(o + 128) = f4tf32(f4scale(a2, 1.f / max(d2, 1)));
    }
}

// ---------------------------------------------------------------------------
// Hand-rolled tf32 mma GEMM (validated). A pre-rounded -> staging is plain copy.
// LAYER1 epilogue stores tf32-rounded x2.
// ---------------------------------------------------------------------------
template <int LAYER>
__global__ __launch_bounds__(256) void gemm_mma_kernel(const float* __restrict__ bias,
                                                       const int* __restrict__ batch) {
    constexpr int KK = (LAYER == 1) ? 128 : 256;
    constexpr int KT = KK / 8;
    const float* H  = (LAYER == 1) ? g_hf1 : g_hf2;
    const float* WP = (LAYER == 1) ? g_wp1 : g_wp2;

    extern __shared__ __align__(16) char dsm[];
    float* s_a = (float*)dsm;                            // [128][68]
    float* s_b = (float*)(dsm + 128 * 68 * 4);           // [64*KK] packed

    int tid = threadIdx.x;
    int wid = tid >> 5, lane = tid & 31;
    int g = lane >> 2, tig = lane & 3;
    int n0 = blockIdx.x * 128;

    for (int q = tid; q < 64 * KK / 4; q += 256)
        ((float4*)s_b)[q] = ((const float4*)WP)[q];

    float d[8][4];
#pragma unroll
    for (int nt = 0; nt < 8; nt++)
#pragma unroll
        for (int c = 0; c < 4; c++) d[nt][c] = 0.f;

    const unsigned* ua = (const unsigned*)s_a;
    int arow0 = (wid * 16 + g) * 68;
    int arow1 = arow0 + 8 * 68;

#pragma unroll
    for (int kc = 0; kc < KK; kc += 64) {
        __syncthreads();
#pragma unroll
        for (int it = 0; it < 8; it++) {
            int q = tid + it * 256;
            int row = q >> 4, c4 = (q & 15) * 4;
            *(float4*)(s_a + row * 68 + c4) =
                *(const float4*)(H + (size_t)(n0 + row) * KK + kc + c4);
        }
        __syncthreads();

        int kt0 = kc >> 3;
#pragma unroll
        for (int k8 = 0; k8 < 8; k8++) {
            int kb = k8 * 8 + tig;
            unsigned a0 = ua[arow0 + kb];
            unsigned a1 = ua[arow1 + kb];
            unsigned a2 = ua[arow0 + kb + 4];
            unsigned a3 = ua[arow1 + kb + 4];
            int bbase = ((kt0 + k8) * 32 + g * 4 + tig) * 2;
#pragma unroll
            for (int nt = 0; nt < 8; nt++) {
                uint2 b = *(const uint2*)(s_b + nt * (KT * 64) + bbase);
                mma_tf32(d[nt], a0, a1, a2, a3, b.x, b.y);
            }
        }
    }

    int r0 = n0 + wid * 16 + g;
    int r1 = r0 + 8;
#pragma unroll
    for (int nt = 0; nt < 8; nt++) {
        int c = nt * 8 + tig * 2;
        float2 bb = *(const float2*)(bias + c);
        float2 v0 = make_float2(fmaxf(d[nt][0] + bb.x, 0.f), fmaxf(d[nt][1] + bb.y, 0.f));
        float2 v1 = make_float2(fmaxf(d[nt][2] + bb.x, 0.f), fmaxf(d[nt][3] + bb.y, 0.f));
        if (LAYER == 1) {
            if (r0 < NN) *(float2*)(g_hf2 + (size_t)r0 * 256 + c) =
                make_float2(tf32r(v0.x), tf32r(v0.y));
            if (r1 < NN) *(float2*)(g_hf2 + (size_t)r1 * 256 + c) =
                make_float2(tf32r(v1.x), tf32r(v1.y));
        } else {
            if (r0 < NN) red_add_v2(&g_pool[batch[r0] * 64 + c], v0);
            if (r1 < NN) red_add_v2(&g_pool[batch[r1] * 64 + c], v1);
        }
    }
}

// ---------------------------------------------------------------------------
// Classifier (graph counts via binary search on sorted batch)
// ---------------------------------------------------------------------------
static __device__ __forceinline__ int lower_bound(const int* b, int v) {
    int lo = 0, hi = NN;
    while (lo < hi) { int m = (lo + hi) >> 1; if (b[m] < v) lo = m + 1; else hi = m; }
    return lo;
}

__global__ void cls_kernel(const int* __restrict__ batch,
                           const float* __restrict__ cw,
                           const float* __restrict__ cb,
                           float* __restrict__ out) {
    int idx = blockIdx.x * blockDim.x + threadIdx.x;
    if (idx >= NG * 10) return;
    int g = idx / 10, c = idx - g * 10;
    int cnt = lower_bound(batch, g + 1) - lower_bound(batch, g);
    float inv = 1.f / max(cnt, 1);
    float acc = 0.f;
#pragma unroll
    for (int k = 0; k < 64; k++) acc = fmaf(g_pool[g * 64 + k], cw[k * 10 + c], acc);
    out[idx] = acc * inv + cb[c];
}

// ---------------------------------------------------------------------------
extern "C" void kernel_launch(void* const* d_in, const int* in_sizes, int n_in,
                              void* d_out, int out_size) {
    const int*   nf    = (const int*)d_in[0];
    const int*   ei    = (const int*)d_in[1];
    const int*   et    = (const int*)d_in[2];
    const int*   batch = (const int*)d_in[3];
    const float* se    = (const float*)d_in[4];
    const float* ce    = (const float*)d_in[5];
    const float* pw    = (const float*)d_in[6];
    const float* pb    = (const float*)d_in[7];
    const float* root1 = (const float*)d_in[8];
    const float* rel1  = (const float*)d_in[9];
    const float* bias1 = (const float*)d_in[10];
    const float* root2 = (const float*)d_in[11];
    const float* rel2  = (const float*)d_in[12];
    const float* bias2 = (const float*)d_in[13];
    const float* cw    = (const float*)d_in[14];
    const float* cb    = (const float*)d_in[15];
    float* out = (float*)d_out;

    const int SMEM1 = 128 * 68 * 4 + 64 * 128 * 4;   // 67584
    const int SMEM2 = 128 * 68 * 4 + 64 * 256 * 4;   // 100352
    cudaFuncSetAttribute(gemm_mma_kernel<1>, cudaFuncAttributeMaxDynamicSharedMemorySize, SMEM1);
    cudaFuncSetAttribute(gemm_mma_kernel<2>, cudaFuncAttributeMaxDynamicSharedMemorySize, SMEM2);

    init_embed_kernel<<<12500, 256>>>(nf, se, ce, pw, pb);
    prep_w_kernel<<<96, 256>>>(root1, rel1, root2, rel2);
    hist_kernel<<<(NE + 255) / 256, 256>>>(ei, et);
    scan_a_kernel<<<98, 1024>>>();
    scan_b_kernel<<<98, 1024>>>();
    fill_kernel<<<(NE + 255) / 256, 256>>>(ei, et);

    gather1_kernel<<<(NN + 31) / 32, 256>>>();
    gemm_mma_kernel<1><<<(NN + 127) / 128, 256, SMEM1>>>(bias1, batch);

    gather2_kernel<<<(NN + 15) / 16, 256>>>();
    gemm_mma_kernel<2><<<(NN + 127) / 128, 256, SMEM2>>>(bias2, batch);

    cls_kernel<<<20, 256>>>(batch, cw, cb, out);
}